// round 4
// baseline (speedup 1.0000x reference)
#include <cuda_runtime.h>
#include <cuda_bf16.h>
#include <cstdint>

// ---------------------------------------------------------------------------
// RWKV7 Tmix forward, B=2 T=2048 C=2048 H=32 N=64
// Pipeline:
//   1) mix_kernel      : token shift + 6 lerps                      (f32)
//   2) sgemm (f32x2)   : r/k/v C×C, low-rank stage-1 (w1/a1/v1/g1)
//   3) sgemm (f32x2)   : low-rank stage-2 (w2/a2/v2/g2)
//   4) post_kernel     : softplus/sigmoid/kk-norm/k,v update + bf16 staging
//   5) scan_kernel     : sequential delta-rule recurrence, writes o and S_out
//   6) gn_kernel       : per-head GroupNorm + r·k·r_k bonus + gate
//   7) sgemm (f32x2)   : (y*g) @ W_o  -> d_out
//   8) tail_kernel     : x[:, -1]     -> d_out
// ---------------------------------------------------------------------------

constexpr int B_ = 2, T_ = 2048, C_ = 2048, H_ = 32, N_ = 64;
constexpr int M_ = B_ * T_;                       // 4096 token rows
constexpr size_t BTC_ = (size_t)B_ * T_ * C_;     // 8,388,608

// ---- scratch: __device__ globals (no dynamic allocation allowed) ----------
__device__ float g_xr[BTC_], g_xw[BTC_], g_xk[BTC_], g_xv[BTC_], g_xa[BTC_], g_xg[BTC_];
__device__ float g_r[BTC_], g_k[BTC_], g_v[BTC_];
__device__ float g_wout[BTC_], g_aout[BTC_], g_vout[BTC_], g_g[BTC_];
__device__ float g_o[BTC_], g_y[BTC_];
__device__ float g_hw[M_ * 64], g_ha[M_ * 64], g_hv[M_ * 32], g_hg[M_ * 128];
// bf16 staging for the scan (reference rounds r,k,v,w,-kk,kk*a to bf16)
__device__ __nv_bfloat16 sb_r[BTC_], sb_k[BTC_], sb_v[BTC_], sb_w[BTC_], sb_a[BTC_], sb_b[BTC_];

// ---------------------------------------------------------------------------
// packed f32x2 helpers (Blackwell: fma.rn.f32x2 doubles FFMA throughput)
// ---------------------------------------------------------------------------
__device__ __forceinline__ unsigned long long pk2dup(float v) {
    unsigned long long r; unsigned u = __float_as_uint(v);
    asm("mov.b64 %0, {%1, %2};" : "=l"(r) : "r"(u), "r"(u));
    return r;
}
__device__ __forceinline__ unsigned long long ffma2(unsigned long long a,
                                                    unsigned long long b,
                                                    unsigned long long c) {
    unsigned long long d;
    asm("fma.rn.f32x2 %0, %1, %2, %3;" : "=l"(d) : "l"(a), "l"(b), "l"(c));
    return d;
}
__device__ __forceinline__ float2 upk2(unsigned long long v) {
    unsigned lo, hi;
    asm("mov.b64 {%0, %1}, %2;" : "=r"(lo), "=r"(hi) : "l"(v));
    return make_float2(__uint_as_float(lo), __uint_as_float(hi));
}

__device__ __forceinline__ float sigm(float x) { return 1.f / (1.f + expf(-x)); }
__device__ __forceinline__ float wredsum(float v) {
#pragma unroll
    for (int o = 16; o; o >>= 1) v += __shfl_xor_sync(0xffffffffu, v, o);
    return v;
}

// ---------------------------------------------------------------------------
// 1) token shift + mixes (vectorized float4)
// ---------------------------------------------------------------------------
__global__ void __launch_bounds__(256) mix_kernel(
    const float4* __restrict__ x4, const float4* __restrict__ sh4,
    const float4* __restrict__ mr, const float4* __restrict__ mw,
    const float4* __restrict__ mk, const float4* __restrict__ mv,
    const float4* __restrict__ ma, const float4* __restrict__ mg)
{
    size_t i = (size_t)blockIdx.x * 256 + threadIdx.x;   // over BTC/4
    int c4 = (int)(i & 511);                              // C/4 = 512
    size_t bt = i >> 9;
    int t = (int)(bt & (T_ - 1));
    float4 xv = x4[i];
    float4 pv = (t == 0) ? sh4[(bt >> 11) * 512 + c4] : x4[i - 512];
    float dx = pv.x - xv.x, dy = pv.y - xv.y, dz = pv.z - xv.z, dw = pv.w - xv.w;
#define MIXOUT(dst, mm) { float4 m = (mm)[c4]; float4 o;                         \
        o.x = fmaf(dx, m.x, xv.x); o.y = fmaf(dy, m.y, xv.y);                    \
        o.z = fmaf(dz, m.z, xv.z); o.w = fmaf(dw, m.w, xv.w);                    \
        ((float4*)(dst))[i] = o; }
    MIXOUT(g_xr, mr) MIXOUT(g_xw, mw) MIXOUT(g_xk, mk)
    MIXOUT(g_xv, mv) MIXOUT(g_xa, ma) MIXOUT(g_xg, mg)
#undef MIXOUT
}

// ---------------------------------------------------------------------------
// 2/3/7) SGEMM: C[M,N] = A[M,K] @ B[K,N], f32, packed-f32x2 inner loop.
// Requires M%128==0, N%BN==0, K%16==0, K%4==0, N%4==0 (all shapes satisfy).
// EPI: 0 none, 1 tanh, 2 sigmoid (applied at store).
// ---------------------------------------------------------------------------
template<int BN, int TN, int EPI>
__global__ void __launch_bounds__(256) sgemm_kernel(
    const float* __restrict__ A, const float* __restrict__ Bm,
    float* __restrict__ Cm, int M, int N, int K)
{
    constexpr int BM = 128, BK = 16, TM = 8;
    constexpr int TN2 = TN / 2;
    __shared__ float As[BK][BM];
    __shared__ float Bs[BK][BN];
    const int tid  = threadIdx.x;
    const int trow = tid >> 4;      // 0..15 -> 8 rows each
    const int tcol = tid & 15;      // 0..15 -> TN cols each
    const int rowBase = blockIdx.y * BM;
    const int colBase = blockIdx.x * BN;

    unsigned long long acc[TM][TN2];
#pragma unroll
    for (int i = 0; i < TM; i++)
#pragma unroll
        for (int j = 0; j < TN2; j++) acc[i][j] = 0ull;  // {0.f, 0.f}

    for (int kt = 0; kt < K; kt += BK) {
        // A tile: BM x BK, stored transposed As[k][m]
        for (int i = tid; i < BM * BK / 4; i += 256) {
            int r = i >> 2, c4 = i & 3;
            const float4 v = *(const float4*)(A + (size_t)(rowBase + r) * K + kt + c4 * 4);
            As[c4 * 4 + 0][r] = v.x; As[c4 * 4 + 1][r] = v.y;
            As[c4 * 4 + 2][r] = v.z; As[c4 * 4 + 3][r] = v.w;
        }
        // B tile: BK x BN row-major
        for (int i = tid; i < BK * BN / 4; i += 256) {
            int r = i / (BN / 4), c4 = i % (BN / 4);
            *(float4*)(&Bs[r][c4 * 4]) =
                *(const float4*)(Bm + (size_t)(kt + r) * N + colBase + c4 * 4);
        }
        __syncthreads();
#pragma unroll
        for (int kk = 0; kk < BK; kk++) {
            const float4 a0 = *(const float4*)(&As[kk][trow * TM]);
            const float4 a1 = *(const float4*)(&As[kk][trow * TM + 4]);
            unsigned long long bf[TN2];
            const unsigned long long* bp = (const unsigned long long*)(&Bs[kk][tcol * TN]);
#pragma unroll
            for (int j = 0; j < TN2; j++) bf[j] = bp[j];
            const float av[8] = {a0.x, a0.y, a0.z, a0.w, a1.x, a1.y, a1.z, a1.w};
#pragma unroll
            for (int i = 0; i < TM; i++) {
                unsigned long long ad = pk2dup(av[i]);
#pragma unroll
                for (int j = 0; j < TN2; j++) acc[i][j] = ffma2(ad, bf[j], acc[i][j]);
            }
        }
        __syncthreads();
    }
#pragma unroll
    for (int i = 0; i < TM; i++) {
        float* crow = Cm + (size_t)(rowBase + trow * TM + i) * N + colBase + tcol * TN;
#pragma unroll
        for (int j = 0; j < TN2; j++) {
            float2 v = upk2(acc[i][j]);
            if (EPI == 1) { v.x = tanhf(v.x); v.y = tanhf(v.y); }
            if (EPI == 2) { v.x = sigm(v.x);  v.y = sigm(v.y); }
            crow[2 * j] = v.x;
            crow[2 * j + 1] = v.y;
        }
    }
}

// ---------------------------------------------------------------------------
// 4) post-GEMM elementwise: one warp per (b,t,h), 2 channels per lane.
// ---------------------------------------------------------------------------
__global__ void __launch_bounds__(256) post_kernel(
    const float* __restrict__ v_first, const float* __restrict__ w0,
    const float* __restrict__ a0, const float* __restrict__ v0,
    const float* __restrict__ kkm, const float* __restrict__ kam)
{
    int g = blockIdx.x * 8 + (threadIdx.x >> 5);          // (b*T+t)*H + h
    int lane = threadIdx.x & 31;
    int h = g & (H_ - 1);
    size_t bt = (size_t)(g >> 5);
    size_t i0 = bt * C_ + (size_t)h * N_ + lane, i1 = i0 + 32;
    int c0 = h * N_ + lane, c1 = c0 + 32;

    // kk = normalize_head(k * k_k)
    float kr0 = g_k[i0], kr1 = g_k[i1];
    float kk0 = kr0 * kkm[c0], kk1 = kr1 * kkm[c1];
    float ss = wredsum(kk0 * kk0 + kk1 * kk1);
    float inv = 1.f / fmaxf(sqrtf(ss), 1e-12f);
    kk0 *= inv; kk1 *= inv;

    // a = sigmoid(a0 + a2-path)
    float aa0 = sigm(a0[c0] + g_aout[i0]);
    float aa1 = sigm(a0[c1] + g_aout[i1]);

    // w = -softplus(-(w0 + w2-path)) - 0.5 (stable)
    float z0 = w0[c0] + g_wout[i0], z1 = w0[c1] + g_wout[i1];
    float u0 = -z0, u1 = -z1;
    float sp0 = fmaxf(u0, 0.f) + log1pf(expf(-fabsf(u0)));
    float sp1 = fmaxf(u1, 0.f) + log1pf(expf(-fabsf(u1)));
    float ww0 = -sp0 - 0.5f, ww1 = -sp1 - 0.5f;

    // v = v + (v_first - v) * sigmoid(v0 + v2-path)
    float sv0 = sigm(v0[c0] + g_vout[i0]);
    float sv1 = sigm(v0[c1] + g_vout[i1]);
    float vr0 = g_v[i0], vr1 = g_v[i1];
    float vv0 = fmaf(v_first[i0] - vr0, sv0, vr0);
    float vv1 = fmaf(v_first[i1] - vr1, sv1, vr1);
    g_v[i0] = vv0; g_v[i1] = vv1;

    // k = k * (1 + (a-1)*k_a)
    float kn0 = kr0 * fmaf(aa0 - 1.f, kam[c0], 1.f);
    float kn1 = kr1 * fmaf(aa1 - 1.f, kam[c1], 1.f);
    g_k[i0] = kn0; g_k[i1] = kn1;

    // bf16 staging for the scan (matches reference's bf16 round-trip)
    sb_r[i0] = __float2bfloat16(g_r[i0]); sb_r[i1] = __float2bfloat16(g_r[i1]);
    sb_k[i0] = __float2bfloat16(kn0);     sb_k[i1] = __float2bfloat16(kn1);
    sb_v[i0] = __float2bfloat16(vv0);     sb_v[i1] = __float2bfloat16(vv1);
    sb_w[i0] = __float2bfloat16(ww0);     sb_w[i1] = __float2bfloat16(ww1);
    sb_a[i0] = __float2bfloat16(-kk0);    sb_a[i1] = __float2bfloat16(-kk1);
    sb_b[i0] = __float2bfloat16(kk0 * aa0); sb_b[i1] = __float2bfloat16(kk1 * aa1);
}

// ---------------------------------------------------------------------------
// 5) sequential scan. One CTA per (b,h); 128 threads; thread (col, half)
//    owns S[half*32 .. half*32+31][col] in registers. Double-buffered shared
//    broadcast + register prefetch of t+1 hides global-load latency; one
//    __syncthreads per step (safe: barrier of step t separates compute(t-1)
//    from stores of step t+1 into the other buffer).
// ---------------------------------------------------------------------------
__global__ void __launch_bounds__(128) scan_kernel(
    const float* __restrict__ wkv0, float* __restrict__ outS)
{
    const int b = blockIdx.x >> 5;       // H=32
    const int h = blockIdx.x & 31;
    const int tid = threadIdx.x;
    const int col = tid >> 1;
    const int half = tid & 1;
    const int ko = half * 32;

    __shared__ float sh[2][6][N_];       // [buf][r,k,v,ew,a,b][n]

    float S[32];
    {
        size_t sbase = (((size_t)b * H_ + h) * N_) * N_;
#pragma unroll
        for (int j = 0; j < 32; j++)
            S[j] = wkv0[sbase + (size_t)(ko + j) * N_ + col];
    }

    const size_t base = ((size_t)b * T_) * C_ + (size_t)h * N_;
    float pr = 0, pk = 0, pv = 0, pw = 0, pa = 0, pb = 0;
    if (tid < 64) {
        size_t idx = base + tid;
        pr = __bfloat162float(sb_r[idx]); pk = __bfloat162float(sb_k[idx]);
        pv = __bfloat162float(sb_v[idx]); pw = __bfloat162float(sb_w[idx]);
        pa = __bfloat162float(sb_a[idx]); pb = __bfloat162float(sb_b[idx]);
    }
    int buf = 0;
    for (int t = 0; t < T_; t++) {
        if (tid < 64) {
            sh[buf][0][tid] = pr; sh[buf][1][tid] = pk; sh[buf][2][tid] = pv;
            sh[buf][3][tid] = expf(pw); sh[buf][4][tid] = pa; sh[buf][5][tid] = pb;
            if (t + 1 < T_) {
                size_t idx = base + (size_t)(t + 1) * C_ + tid;
                pr = __bfloat162float(sb_r[idx]); pk = __bfloat162float(sb_k[idx]);
                pv = __bfloat162float(sb_v[idx]); pw = __bfloat162float(sb_w[idx]);
                pa = __bfloat162float(sb_a[idx]); pb = __bfloat162float(sb_b[idx]);
            }
        }
        __syncthreads();
        const float* shr = sh[buf][0]; const float* shk = sh[buf][1];
        const float* shv = sh[buf][2]; const float* she = sh[buf][3];
        const float* sha = sh[buf][4]; const float* shb = sh[buf][5];

        float sa = 0.f;
#pragma unroll
        for (int j = 0; j < 32; j++) sa = fmaf(sha[ko + j], S[j], sa);
        sa += __shfl_xor_sync(0xffffffffu, sa, 1);

        const float vt = shv[col];
        float o = 0.f;
#pragma unroll
        for (int j = 0; j < 32; j++) {
            float sn = fmaf(S[j], she[ko + j], fmaf(shb[ko + j], sa, shk[ko + j] * vt));
            S[j] = sn;
            o = fmaf(shr[ko + j], sn, o);
        }
        o += __shfl_xor_sync(0xffffffffu, o, 1);
        if (half == 0) g_o[base + (size_t)t * C_ + col] = o;
        buf ^= 1;
    }
    {
        size_t sbase = (((size_t)b * H_ + h) * N_) * N_;
#pragma unroll
        for (int j = 0; j < 32; j++)
            outS[sbase + (size_t)(ko + j) * N_ + col] = S[j];
    }
}

// ---------------------------------------------------------------------------
// 6) GroupNorm (per head) + r·k·r_k bonus + gate
// ---------------------------------------------------------------------------
__global__ void __launch_bounds__(256) gn_kernel(
    const float* __restrict__ rk, const float* __restrict__ lnw,
    const float* __restrict__ lnb)
{
    int g = blockIdx.x * 8 + (threadIdx.x >> 5);
    int lane = threadIdx.x & 31;
    int h = g & (H_ - 1);
    size_t bt = (size_t)(g >> 5);
    size_t i0 = bt * C_ + (size_t)h * N_ + lane, i1 = i0 + 32;
    int c0 = h * N_ + lane, c1 = c0 + 32;

    float o0 = g_o[i0], o1 = g_o[i1];
    float mu = wredsum(o0 + o1) * (1.f / 64.f);
    float d0 = o0 - mu, d1 = o1 - mu;
    float var = wredsum(d0 * d0 + d1 * d1) * (1.f / 64.f);
    float inv = 1.f / sqrtf(var + 6.4e-4f);    // EPS_GN = 1e-5 * 8^2
    float y0 = fmaf(d0 * inv, lnw[c0], lnb[c0]);
    float y1 = fmaf(d1 * inv, lnw[c1], lnb[c1]);
    float dot = wredsum(g_r[i0] * g_k[i0] * rk[c0] + g_r[i1] * g_k[i1] * rk[c1]);
    y0 = fmaf(dot, g_v[i0], y0);
    y1 = fmaf(dot, g_v[i1], y1);
    g_y[i0] = y0 * g_g[i0];
    g_y[i1] = y1 * g_g[i1];
}

// 8) x[:, -1] passthrough
__global__ void tail_kernel(const float* __restrict__ x, float* __restrict__ outx) {
    int i = blockIdx.x * 256 + threadIdx.x;   // B*C = 4096
    int b = i >> 11, c = i & (C_ - 1);
    outx[i] = x[((size_t)b * T_ + (T_ - 1)) * C_ + c];
}

// ---------------------------------------------------------------------------
extern "C" void kernel_launch(void* const* d_in, const int* in_sizes, int n_in,
                              void* d_out, int out_size) {
    const float* x    = (const float*)d_in[0];
    const float* shf  = (const float*)d_in[1];
    const float* wkv0 = (const float*)d_in[2];
    const float* vf   = (const float*)d_in[3];
    const float* mr   = (const float*)d_in[4];
    const float* mw   = (const float*)d_in[5];
    const float* mk   = (const float*)d_in[6];
    const float* mv   = (const float*)d_in[7];
    const float* ma   = (const float*)d_in[8];
    const float* mg   = (const float*)d_in[9];
    const float* w0   = (const float*)d_in[10];
    const float* w1   = (const float*)d_in[11];
    const float* w2   = (const float*)d_in[12];
    const float* a0   = (const float*)d_in[13];
    const float* a1   = (const float*)d_in[14];
    const float* a2   = (const float*)d_in[15];
    const float* v0   = (const float*)d_in[16];
    const float* v1   = (const float*)d_in[17];
    const float* v2   = (const float*)d_in[18];
    const float* g1   = (const float*)d_in[19];
    const float* g2   = (const float*)d_in[20];
    const float* kkm  = (const float*)d_in[21];
    const float* kam  = (const float*)d_in[22];
    const float* rk   = (const float*)d_in[23];
    const float* Wr   = (const float*)d_in[24];
    const float* Wk   = (const float*)d_in[25];
    const float* Wv   = (const float*)d_in[26];
    const float* Wo   = (const float*)d_in[27];
    const float* lnw  = (const float*)d_in[28];
    const float* lnb  = (const float*)d_in[29];

    float* out   = (float*)d_out;                 // [B,T,C]
    float* out_x = out + BTC_;                    // [B,C]
    float* out_S = out_x + (size_t)B_ * C_;       // [B,H,N,N]

    float *p_xr, *p_xw, *p_xk, *p_xv, *p_xa, *p_xg;
    float *p_r, *p_k, *p_v, *p_wout, *p_aout, *p_vout, *p_g, *p_y;
    float *p_hw, *p_ha, *p_hv, *p_hg;
    cudaGetSymbolAddress((void**)&p_xr, g_xr);
    cudaGetSymbolAddress((void**)&p_xw, g_xw);
    cudaGetSymbolAddress((void**)&p_xk, g_xk);
    cudaGetSymbolAddress((void**)&p_xv, g_xv);
    cudaGetSymbolAddress((void**)&p_xa, g_xa);
    cudaGetSymbolAddress((void**)&p_xg, g_xg);
    cudaGetSymbolAddress((void**)&p_r,  g_r);
    cudaGetSymbolAddress((void**)&p_k,  g_k);
    cudaGetSymbolAddress((void**)&p_v,  g_v);
    cudaGetSymbolAddress((void**)&p_wout, g_wout);
    cudaGetSymbolAddress((void**)&p_aout, g_aout);
    cudaGetSymbolAddress((void**)&p_vout, g_vout);
    cudaGetSymbolAddress((void**)&p_g,  g_g);
    cudaGetSymbolAddress((void**)&p_y,  g_y);
    cudaGetSymbolAddress((void**)&p_hw, g_hw);
    cudaGetSymbolAddress((void**)&p_ha, g_ha);
    cudaGetSymbolAddress((void**)&p_hv, g_hv);
    cudaGetSymbolAddress((void**)&p_hg, g_hg);

    // 1) token shift + mixes
    mix_kernel<<<(unsigned)(BTC_ / 4 / 256), 256>>>(
        (const float4*)x, (const float4*)shf,
        (const float4*)mr, (const float4*)mw, (const float4*)mk,
        (const float4*)mv, (const float4*)ma, (const float4*)mg);

    dim3 gBig(C_ / 128, M_ / 128);
    dim3 gOne(1, M_ / 128);

    // 2) big projections + low-rank stage 1
    sgemm_kernel<128, 8, 0><<<gBig, 256>>>(p_xr, Wr, p_r, M_, C_, C_);
    sgemm_kernel<128, 8, 0><<<gBig, 256>>>(p_xk, Wk, p_k, M_, C_, C_);
    sgemm_kernel<128, 8, 0><<<gBig, 256>>>(p_xv, Wv, p_v, M_, C_, C_);
    sgemm_kernel< 64, 4, 1><<<gOne, 256>>>(p_xw, w1, p_hw, M_, 64, C_);   // tanh
    sgemm_kernel< 64, 4, 0><<<gOne, 256>>>(p_xa, a1, p_ha, M_, 64, C_);
    sgemm_kernel< 32, 2, 0><<<gOne, 256>>>(p_xv, v1, p_hv, M_, 32, C_);
    sgemm_kernel<128, 8, 2><<<gOne, 256>>>(p_xg, g1, p_hg, M_, 128, C_);  // sigmoid

    // 3) low-rank stage 2
    sgemm_kernel<128, 8, 0><<<gBig, 256>>>(p_hw, w2, p_wout, M_, C_, 64);
    sgemm_kernel<128, 8, 0><<<gBig, 256>>>(p_ha, a2, p_aout, M_, C_, 64);
    sgemm_kernel<128, 8, 0><<<gBig, 256>>>(p_hv, v2, p_vout, M_, C_, 32);
    sgemm_kernel<128, 8, 0><<<gBig, 256>>>(p_hg, g2, p_g,    M_, C_, 128);

    // 4) elementwise post + bf16 staging
    post_kernel<<<(B_ * T_ * H_) / 8, 256>>>(vf, w0, a0, v0, kkm, kam);

    // 5) recurrence (also writes final state to d_out)
    scan_kernel<<<B_ * H_, 128>>>(wkv0, out_S);

    // 6) GroupNorm + bonus + gate
    gn_kernel<<<(B_ * T_ * H_) / 8, 256>>>(rk, lnw, lnb);

    // 7) output projection straight into d_out
    sgemm_kernel<128, 8, 0><<<gBig, 256>>>(p_y, Wo, out, M_, C_, C_);

    // 8) x[:, -1]
    tail_kernel<<<(B_ * C_) / 256, 256>>>(x, out_x);
}

// round 6
// speedup vs baseline: 1.3523x; 1.3523x over previous
#include <cuda_runtime.h>
#include <cuda_bf16.h>
#include <cstdint>

// ---------------------------------------------------------------------------
// RWKV7 Tmix forward, B=2 T=2048 C=2048 H=32 N=64   (R4 kernel, resubmitted
// after a container-level infra failure produced no measurement)
//   1) mix_kernel   : token shift + 6 lerps
//   2) sgemm128     : r/k/v projections (cp.async double-buffered f32x2 GEMM)
//   3) s1_kernel    : all 4 low-rank stage-1 GEMMs fused (tanh/sigmoid epi)
//   4) sgemm128     : low-rank stage-2 (w2/a2/v2/g2)
//   5) post_kernel  : softplus/sigmoid/kk-norm/k,v update + bf16 staging
//   6) scan_kernel  : sequential delta-rule recurrence (packed f32x2)
//   7) gn_kernel    : per-head GroupNorm + r.k.r_k bonus + gate
//   8) sgemm128     : (y*g) @ W_o -> d_out ; tail_kernel: x[:,-1]
// ---------------------------------------------------------------------------

constexpr int B_ = 2, T_ = 2048, C_ = 2048, H_ = 32, N_ = 64;
constexpr int M_ = B_ * T_;                       // 4096 token rows
constexpr size_t BTC_ = (size_t)B_ * T_ * C_;     // 8,388,608

// ---- scratch: __device__ globals ------------------------------------------
__device__ float g_xr[BTC_], g_xw[BTC_], g_xk[BTC_], g_xv[BTC_], g_xa[BTC_], g_xg[BTC_];
__device__ float g_r[BTC_], g_k[BTC_], g_v[BTC_];
__device__ float g_wout[BTC_], g_aout[BTC_], g_vout[BTC_], g_g[BTC_];
__device__ float g_o[BTC_], g_y[BTC_];
__device__ float g_hw[M_ * 64], g_ha[M_ * 64], g_hv[M_ * 32], g_hg[M_ * 128];
__device__ __nv_bfloat16 sb_r[BTC_], sb_k[BTC_], sb_v[BTC_], sb_w[BTC_], sb_a[BTC_], sb_b[BTC_];

// ---------------------------------------------------------------------------
// packed f32x2 + cp.async helpers
// ---------------------------------------------------------------------------
__device__ __forceinline__ unsigned long long pk2dup(float v) {
    unsigned long long r; unsigned u = __float_as_uint(v);
    asm("mov.b64 %0, {%1, %2};" : "=l"(r) : "r"(u), "r"(u));
    return r;
}
__device__ __forceinline__ unsigned long long pk2(float a, float b) {
    unsigned long long r;
    asm("mov.b64 %0, {%1, %2};" : "=l"(r) : "r"(__float_as_uint(a)), "r"(__float_as_uint(b)));
    return r;
}
__device__ __forceinline__ unsigned long long ffma2(unsigned long long a,
                                                    unsigned long long b,
                                                    unsigned long long c) {
    unsigned long long d;
    asm("fma.rn.f32x2 %0, %1, %2, %3;" : "=l"(d) : "l"(a), "l"(b), "l"(c));
    return d;
}
__device__ __forceinline__ unsigned long long mul2(unsigned long long a,
                                                   unsigned long long b) {
    unsigned long long d;
    asm("mul.rn.f32x2 %0, %1, %2;" : "=l"(d) : "l"(a), "l"(b));
    return d;
}
__device__ __forceinline__ float2 upk2(unsigned long long v) {
    unsigned lo, hi;
    asm("mov.b64 {%0, %1}, %2;" : "=r"(lo), "=r"(hi) : "l"(v));
    return make_float2(__uint_as_float(lo), __uint_as_float(hi));
}
__device__ __forceinline__ void cp16(uint32_t s, const void* g) {
    asm volatile("cp.async.cg.shared.global [%0], [%1], 16;" :: "r"(s), "l"(g));
}
__device__ __forceinline__ void cp_commit() { asm volatile("cp.async.commit_group;"); }
__device__ __forceinline__ void cp_wait0()  { asm volatile("cp.async.wait_group 0;"); }

__device__ __forceinline__ float sigm(float x) { return 1.f / (1.f + expf(-x)); }
__device__ __forceinline__ float wredsum(float v) {
#pragma unroll
    for (int o = 16; o; o >>= 1) v += __shfl_xor_sync(0xffffffffu, v, o);
    return v;
}

// ---------------------------------------------------------------------------
// 1) token shift + mixes (vectorized float4)
// ---------------------------------------------------------------------------
__global__ void __launch_bounds__(256) mix_kernel(
    const float4* __restrict__ x4, const float4* __restrict__ sh4,
    const float4* __restrict__ mr, const float4* __restrict__ mw,
    const float4* __restrict__ mk, const float4* __restrict__ mv,
    const float4* __restrict__ ma, const float4* __restrict__ mg)
{
    size_t i = (size_t)blockIdx.x * 256 + threadIdx.x;   // over BTC/4
    int c4 = (int)(i & 511);                              // C/4 = 512
    size_t bt = i >> 9;
    int t = (int)(bt & (T_ - 1));
    float4 xv = x4[i];
    float4 pv = (t == 0) ? sh4[(bt >> 11) * 512 + c4] : x4[i - 512];
    float dx = pv.x - xv.x, dy = pv.y - xv.y, dz = pv.z - xv.z, dw = pv.w - xv.w;
#define MIXOUT(dst, mm) { float4 m = (mm)[c4]; float4 o;                         \
        o.x = fmaf(dx, m.x, xv.x); o.y = fmaf(dy, m.y, xv.y);                    \
        o.z = fmaf(dz, m.z, xv.z); o.w = fmaf(dw, m.w, xv.w);                    \
        ((float4*)(dst))[i] = o; }
    MIXOUT(g_xr, mr) MIXOUT(g_xw, mw) MIXOUT(g_xk, mk)
    MIXOUT(g_xv, mv) MIXOUT(g_xa, ma) MIXOUT(g_xg, mg)
#undef MIXOUT
}

// ---------------------------------------------------------------------------
// 2/4/8) SGEMM 128x128 tile, BK=16, cp.async double-buffered, f32x2 core.
// Requires M%128==0, N%128==0, K%16==0.  smem = 36 KB static.
// ---------------------------------------------------------------------------
__global__ void __launch_bounds__(256, 2) sgemm128(
    const float* __restrict__ A, const float* __restrict__ Bm,
    float* __restrict__ Cm, int M, int N, int K)
{
    constexpr int BM = 128, BN = 128, BK = 16, BKP = 20;   // BKP*4B = 80B (16B-aligned)
    __shared__ __align__(16) float As[2][BM * BKP];
    __shared__ __align__(16) float Bs[2][BK * BN];

    const int tid  = threadIdx.x;
    const int trow = tid >> 4;       // 0..15 -> 8 rows each
    const int tcol = tid & 15;       // 0..15 -> 8 cols each
    const int rowBase = blockIdx.y * BM;
    const int colBase = blockIdx.x * BN;

    const uint32_t sAs = (uint32_t)__cvta_generic_to_shared(As);
    const uint32_t sBs = (uint32_t)__cvta_generic_to_shared(Bs);

    // per-thread async-copy chunk coordinates (2 A + 2 B 16B chunks per kt)
    const int am0 = tid >> 2,          ac0 = (tid & 3) * 4;
    const int am1 = (tid + 256) >> 2,  ac1 = ((tid + 256) & 3) * 4;
    const int br0 = tid >> 5,          bc0 = (tid & 31) * 4;
    const int br1 = (tid + 256) >> 5,  bc1 = ((tid + 256) & 31) * 4;
    const float* Abase = A + (size_t)rowBase * K;
    const float* Bbase = Bm + colBase;

    unsigned long long acc[8][4];
#pragma unroll
    for (int i = 0; i < 8; i++)
#pragma unroll
        for (int j = 0; j < 4; j++) acc[i][j] = 0ull;

#define LOAD_TILE(kt, s) {                                                        \
        cp16(sAs + ((s) * BM * BKP + am0 * BKP + ac0) * 4,                        \
             Abase + (size_t)am0 * K + (kt) + ac0);                               \
        cp16(sAs + ((s) * BM * BKP + am1 * BKP + ac1) * 4,                        \
             Abase + (size_t)am1 * K + (kt) + ac1);                               \
        cp16(sBs + ((s) * BK * BN + br0 * BN + bc0) * 4,                          \
             Bbase + (size_t)((kt) + br0) * N + bc0);                             \
        cp16(sBs + ((s) * BK * BN + br1 * BN + bc1) * 4,                          \
             Bbase + (size_t)((kt) + br1) * N + bc1);                             \
        cp_commit(); }

    const int NT = K / BK;
    LOAD_TILE(0, 0)
    for (int t = 0; t < NT; t++) {
        cp_wait0();
        __syncthreads();
        if (t + 1 < NT) LOAD_TILE((t + 1) * BK, (t + 1) & 1)
        const float* as = As[t & 1] + trow * 8 * BKP;
        const float* bs = Bs[t & 1] + tcol * 8;
#pragma unroll
        for (int kk = 0; kk < BK; kk++) {
            const unsigned long long* bp = (const unsigned long long*)(bs + kk * BN);
            unsigned long long b0 = bp[0], b1 = bp[1], b2 = bp[2], b3 = bp[3];
#pragma unroll
            for (int i = 0; i < 8; i++) {
                unsigned long long ad = pk2dup(as[i * BKP + kk]);
                acc[i][0] = ffma2(ad, b0, acc[i][0]);
                acc[i][1] = ffma2(ad, b1, acc[i][1]);
                acc[i][2] = ffma2(ad, b2, acc[i][2]);
                acc[i][3] = ffma2(ad, b3, acc[i][3]);
            }
        }
        __syncthreads();
    }
#undef LOAD_TILE

#pragma unroll
    for (int i = 0; i < 8; i++) {
        float* crow = Cm + (size_t)(rowBase + trow * 8 + i) * N + colBase + tcol * 8;
        float2 v0 = upk2(acc[i][0]), v1 = upk2(acc[i][1]);
        float2 v2 = upk2(acc[i][2]), v3 = upk2(acc[i][3]);
        *(float4*)crow       = make_float4(v0.x, v0.y, v1.x, v1.y);
        *(float4*)(crow + 4) = make_float4(v2.x, v2.y, v3.x, v3.y);
    }
}

// ---------------------------------------------------------------------------
// 3) fused stage-1 low-rank GEMMs: z selects {w1:tanh, a1, v1, g1:sigmoid}.
//    BM=128, BN=32, BK=16, K=2048. grid (4, M/128, 4); excess x-tiles exit.
// ---------------------------------------------------------------------------
__global__ void __launch_bounds__(256, 2) s1_kernel(
    const float* __restrict__ w1, const float* __restrict__ a1,
    const float* __restrict__ v1, const float* __restrict__ g1)
{
    constexpr int BM = 128, BN = 32, BK = 16, BKP = 20, K = C_;
    const int z = blockIdx.z;
    const int Nz = (z == 2) ? 32 : (z == 3 ? 128 : 64);
    if (blockIdx.x * BN >= Nz) return;

    const float* A  = (z == 0) ? g_xw : (z == 1) ? g_xa : (z == 2) ? g_xv : g_xg;
    const float* Bm = (z == 0) ? w1   : (z == 1) ? a1   : (z == 2) ? v1   : g1;
    float* Cm       = (z == 0) ? g_hw : (z == 1) ? g_ha : (z == 2) ? g_hv : g_hg;

    __shared__ __align__(16) float As[2][BM * BKP];
    __shared__ __align__(16) float Bs[2][BK * BN];

    const int tid  = threadIdx.x;
    const int trow = tid >> 3;       // 0..31 -> 4 rows each
    const int tcol = tid & 7;        // 0..7  -> 4 cols each
    const int rowBase = blockIdx.y * BM;
    const int colBase = blockIdx.x * BN;

    const uint32_t sAs = (uint32_t)__cvta_generic_to_shared(As);
    const uint32_t sBs = (uint32_t)__cvta_generic_to_shared(Bs);
    const int am0 = tid >> 2,         ac0 = (tid & 3) * 4;
    const int am1 = (tid + 256) >> 2, ac1 = ((tid + 256) & 3) * 4;
    const int br = tid >> 3, bc = (tid & 7) * 4;      // 128 B-chunks; tid<128 loads
    const float* Abase = A + (size_t)rowBase * K;
    const float* Bbase = Bm + colBase;

    unsigned long long acc[4][2];
#pragma unroll
    for (int i = 0; i < 4; i++) { acc[i][0] = 0ull; acc[i][1] = 0ull; }

#define LOAD_TILE1(kt, s) {                                                       \
        cp16(sAs + ((s) * BM * BKP + am0 * BKP + ac0) * 4,                        \
             Abase + (size_t)am0 * K + (kt) + ac0);                               \
        cp16(sAs + ((s) * BM * BKP + am1 * BKP + ac1) * 4,                        \
             Abase + (size_t)am1 * K + (kt) + ac1);                               \
        if (tid < 128)                                                            \
            cp16(sBs + ((s) * BK * BN + br * BN + bc) * 4,                        \
                 Bbase + (size_t)((kt) + br) * Nz + bc);                          \
        cp_commit(); }

    const int NT = K / BK;
    LOAD_TILE1(0, 0)
    for (int t = 0; t < NT; t++) {
        cp_wait0();
        __syncthreads();
        if (t + 1 < NT) LOAD_TILE1((t + 1) * BK, (t + 1) & 1)
        const float* as = As[t & 1] + trow * 4 * BKP;
        const float* bs = Bs[t & 1] + tcol * 4;
#pragma unroll
        for (int kk = 0; kk < BK; kk++) {
            const unsigned long long* bp = (const unsigned long long*)(bs + kk * BN);
            unsigned long long b0 = bp[0], b1 = bp[1];
#pragma unroll
            for (int i = 0; i < 4; i++) {
                unsigned long long ad = pk2dup(as[i * BKP + kk]);
                acc[i][0] = ffma2(ad, b0, acc[i][0]);
                acc[i][1] = ffma2(ad, b1, acc[i][1]);
            }
        }
        __syncthreads();
    }
#undef LOAD_TILE1

#pragma unroll
    for (int i = 0; i < 4; i++) {
        float* crow = Cm + (size_t)(rowBase + trow * 4 + i) * Nz + colBase + tcol * 4;
        float2 v0 = upk2(acc[i][0]), v1 = upk2(acc[i][1]);
        float4 o = make_float4(v0.x, v0.y, v1.x, v1.y);
        if (z == 0) { o.x = tanhf(o.x); o.y = tanhf(o.y); o.z = tanhf(o.z); o.w = tanhf(o.w); }
        if (z == 3) { o.x = sigm(o.x);  o.y = sigm(o.y);  o.z = sigm(o.z);  o.w = sigm(o.w); }
        *(float4*)crow = o;
    }
}

// ---------------------------------------------------------------------------
// 5) post-GEMM elementwise: one warp per (b,t,h), 2 channels per lane.
// ---------------------------------------------------------------------------
__global__ void __launch_bounds__(256) post_kernel(
    const float* __restrict__ v_first, const float* __restrict__ w0,
    const float* __restrict__ a0, const float* __restrict__ v0,
    const float* __restrict__ kkm, const float* __restrict__ kam)
{
    int g = blockIdx.x * 8 + (threadIdx.x >> 5);          // (b*T+t)*H + h
    int lane = threadIdx.x & 31;
    int h = g & (H_ - 1);
    size_t bt = (size_t)(g >> 5);
    size_t i0 = bt * C_ + (size_t)h * N_ + lane, i1 = i0 + 32;
    int c0 = h * N_ + lane, c1 = c0 + 32;

    float kr0 = g_k[i0], kr1 = g_k[i1];
    float kk0 = kr0 * kkm[c0], kk1 = kr1 * kkm[c1];
    float ss = wredsum(kk0 * kk0 + kk1 * kk1);
    float inv = 1.f / fmaxf(sqrtf(ss), 1e-12f);
    kk0 *= inv; kk1 *= inv;

    float aa0 = sigm(a0[c0] + g_aout[i0]);
    float aa1 = sigm(a0[c1] + g_aout[i1]);

    float z0 = w0[c0] + g_wout[i0], z1 = w0[c1] + g_wout[i1];
    float u0 = -z0, u1 = -z1;
    float sp0 = fmaxf(u0, 0.f) + log1pf(expf(-fabsf(u0)));
    float sp1 = fmaxf(u1, 0.f) + log1pf(expf(-fabsf(u1)));
    float ww0 = -sp0 - 0.5f, ww1 = -sp1 - 0.5f;

    float sv0 = sigm(v0[c0] + g_vout[i0]);
    float sv1 = sigm(v0[c1] + g_vout[i1]);
    float vr0 = g_v[i0], vr1 = g_v[i1];
    float vv0 = fmaf(v_first[i0] - vr0, sv0, vr0);
    float vv1 = fmaf(v_first[i1] - vr1, sv1, vr1);
    g_v[i0] = vv0; g_v[i1] = vv1;

    float kn0 = kr0 * fmaf(aa0 - 1.f, kam[c0], 1.f);
    float kn1 = kr1 * fmaf(aa1 - 1.f, kam[c1], 1.f);
    g_k[i0] = kn0; g_k[i1] = kn1;

    sb_r[i0] = __float2bfloat16(g_r[i0]); sb_r[i1] = __float2bfloat16(g_r[i1]);
    sb_k[i0] = __float2bfloat16(kn0);     sb_k[i1] = __float2bfloat16(kn1);
    sb_v[i0] = __float2bfloat16(vv0);     sb_v[i1] = __float2bfloat16(vv1);
    sb_w[i0] = __float2bfloat16(ww0);     sb_w[i1] = __float2bfloat16(ww1);
    sb_a[i0] = __float2bfloat16(-kk0);    sb_a[i1] = __float2bfloat16(-kk1);
    sb_b[i0] = __float2bfloat16(kk0 * aa0); sb_b[i1] = __float2bfloat16(kk1 * aa1);
}

// ---------------------------------------------------------------------------
// 6) sequential scan, packed f32x2 state. One CTA per (b,h); 128 threads;
//    thread (col, half) owns S[half*32 .. +31][col] as 16 f32x2 pairs.
// ---------------------------------------------------------------------------
__global__ void __launch_bounds__(128) scan_kernel(
    const float* __restrict__ wkv0, float* __restrict__ outS)
{
    const int b = blockIdx.x >> 5;       // H=32
    const int h = blockIdx.x & 31;
    const int tid = threadIdx.x;
    const int col = tid >> 1;
    const int half = tid & 1;
    const int ko = half * 32;

    __shared__ __align__(16) float sh[2][6][N_];   // [buf][r,k,v,ew,a,b][n]

    unsigned long long S2[16];
    {
        size_t sbase = (((size_t)b * H_ + h) * N_) * N_;
#pragma unroll
        for (int j = 0; j < 16; j++)
            S2[j] = pk2(wkv0[sbase + (size_t)(ko + 2 * j) * N_ + col],
                        wkv0[sbase + (size_t)(ko + 2 * j + 1) * N_ + col]);
    }

    const size_t base = ((size_t)b * T_) * C_ + (size_t)h * N_;
    float pr = 0, pk = 0, pv = 0, pw = 0, pa = 0, pb = 0;
    if (tid < 64) {
        size_t idx = base + tid;
        pr = __bfloat162float(sb_r[idx]); pk = __bfloat162float(sb_k[idx]);
        pv = __bfloat162float(sb_v[idx]); pw = __bfloat162float(sb_w[idx]);
        pa = __bfloat162float(sb_a[idx]); pb = __bfloat162float(sb_b[idx]);
    }
    int buf = 0;
    for (int t = 0; t < T_; t++) {
        if (tid < 64) {
            sh[buf][0][tid] = pr; sh[buf][1][tid] = pk; sh[buf][2][tid] = pv;
            sh[buf][3][tid] = expf(pw); sh[buf][4][tid] = pa; sh[buf][5][tid] = pb;
            if (t + 1 < T_) {
                size_t idx = base + (size_t)(t + 1) * C_ + tid;
                pr = __bfloat162float(sb_r[idx]); pk = __bfloat162float(sb_k[idx]);
                pv = __bfloat162float(sb_v[idx]); pw = __bfloat162float(sb_w[idx]);
                pa = __bfloat162float(sb_a[idx]); pb = __bfloat162float(sb_b[idx]);
            }
        }
        __syncthreads();
        const unsigned long long* r2 = (const unsigned long long*)(&sh[buf][0][ko]);
        const unsigned long long* k2 = (const unsigned long long*)(&sh[buf][1][ko]);
        const unsigned long long* e2 = (const unsigned long long*)(&sh[buf][3][ko]);
        const unsigned long long* a2 = (const unsigned long long*)(&sh[buf][4][ko]);
        const unsigned long long* b2 = (const unsigned long long*)(&sh[buf][5][ko]);

        // sa = a . S(col)   (2-way split chain)
        unsigned long long sa2a = 0ull, sa2b = 0ull;
#pragma unroll
        for (int j = 0; j < 16; j += 2) {
            sa2a = ffma2(a2[j],     S2[j],     sa2a);
            sa2b = ffma2(a2[j + 1], S2[j + 1], sa2b);
        }
        float2 sp = upk2(sa2a), sq = upk2(sa2b);
        float sa = (sp.x + sp.y) + (sq.x + sq.y);
        sa += __shfl_xor_sync(0xffffffffu, sa, 1);

        const float vt = sh[buf][2][col];
        const unsigned long long sad = pk2dup(sa), vtd = pk2dup(vt);
        unsigned long long o2a = 0ull, o2b = 0ull;
#pragma unroll
        for (int j = 0; j < 16; j += 2) {
            unsigned long long t0 = ffma2(b2[j],     sad, mul2(k2[j],     vtd));
            unsigned long long t1 = ffma2(b2[j + 1], sad, mul2(k2[j + 1], vtd));
            S2[j]     = ffma2(S2[j],     e2[j],     t0);
            S2[j + 1] = ffma2(S2[j + 1], e2[j + 1], t1);
            o2a = ffma2(r2[j],     S2[j],     o2a);
            o2b = ffma2(r2[j + 1], S2[j + 1], o2b);
        }
        float2 op = upk2(o2a), oq = upk2(o2b);
        float o = (op.x + op.y) + (oq.x + oq.y);
        o += __shfl_xor_sync(0xffffffffu, o, 1);
        if (half == 0) g_o[base + (size_t)t * C_ + col] = o;
        buf ^= 1;
    }
    {
        size_t sbase = (((size_t)b * H_ + h) * N_) * N_;
#pragma unroll
        for (int j = 0; j < 16; j++) {
            float2 v = upk2(S2[j]);
            outS[sbase + (size_t)(ko + 2 * j) * N_ + col]     = v.x;
            outS[sbase + (size_t)(ko + 2 * j + 1) * N_ + col] = v.y;
        }
    }
}

// ---------------------------------------------------------------------------
// 7) GroupNorm (per head) + r.k.r_k bonus + gate
// ---------------------------------------------------------------------------
__global__ void __launch_bounds__(256) gn_kernel(
    const float* __restrict__ rk, const float* __restrict__ lnw,
    const float* __restrict__ lnb)
{
    int g = blockIdx.x * 8 + (threadIdx.x >> 5);
    int lane = threadIdx.x & 31;
    int h = g & (H_ - 1);
    size_t bt = (size_t)(g >> 5);
    size_t i0 = bt * C_ + (size_t)h * N_ + lane, i1 = i0 + 32;
    int c0 = h * N_ + lane, c1 = c0 + 32;

    float o0 = g_o[i0], o1 = g_o[i1];
    float mu = wredsum(o0 + o1) * (1.f / 64.f);
    float d0 = o0 - mu, d1 = o1 - mu;
    float var = wredsum(d0 * d0 + d1 * d1) * (1.f / 64.f);
    float inv = 1.f / sqrtf(var + 6.4e-4f);    // EPS_GN = 1e-5 * 8^2
    float y0 = fmaf(d0 * inv, lnw[c0], lnb[c0]);
    float y1 = fmaf(d1 * inv, lnw[c1], lnb[c1]);
    float dot = wredsum(g_r[i0] * g_k[i0] * rk[c0] + g_r[i1] * g_k[i1] * rk[c1]);
    y0 = fmaf(dot, g_v[i0], y0);
    y1 = fmaf(dot, g_v[i1], y1);
    g_y[i0] = y0 * g_g[i0];
    g_y[i1] = y1 * g_g[i1];
}

// 8b) x[:, -1] passthrough
__global__ void tail_kernel(const float* __restrict__ x, float* __restrict__ outx) {
    int i = blockIdx.x * 256 + threadIdx.x;   // B*C = 4096
    int b = i >> 11, c = i & (C_ - 1);
    outx[i] = x[((size_t)b * T_ + (T_ - 1)) * C_ + c];
}

// ---------------------------------------------------------------------------
extern "C" void kernel_launch(void* const* d_in, const int* in_sizes, int n_in,
                              void* d_out, int out_size) {
    const float* x    = (const float*)d_in[0];
    const float* shf  = (const float*)d_in[1];
    const float* wkv0 = (const float*)d_in[2];
    const float* vf   = (const float*)d_in[3];
    const float* mr   = (const float*)d_in[4];
    const float* mw   = (const float*)d_in[5];
    const float* mk   = (const float*)d_in[6];
    const float* mv   = (const float*)d_in[7];
    const float* ma   = (const float*)d_in[8];
    const float* mg   = (const float*)d_in[9];
    const float* w0   = (const float*)d_in[10];
    const float* w1   = (const float*)d_in[11];
    const float* w2   = (const float*)d_in[12];
    const float* a0   = (const float*)d_in[13];
    const float* a1   = (const float*)d_in[14];
    const float* a2   = (const float*)d_in[15];
    const float* v0   = (const float*)d_in[16];
    const float* v1   = (const float*)d_in[17];
    const float* v2   = (const float*)d_in[18];
    const float* g1   = (const float*)d_in[19];
    const float* g2   = (const float*)d_in[20];
    const float* kkm  = (const float*)d_in[21];
    const float* kam  = (const float*)d_in[22];
    const float* rk   = (const float*)d_in[23];
    const float* Wr   = (const float*)d_in[24];
    const float* Wk   = (const float*)d_in[25];
    const float* Wv   = (const float*)d_in[26];
    const float* Wo   = (const float*)d_in[27];
    const float* lnw  = (const float*)d_in[28];
    const float* lnb  = (const float*)d_in[29];

    float* out   = (float*)d_out;                 // [B,T,C]
    float* out_x = out + BTC_;                    // [B,C]
    float* out_S = out_x + (size_t)B_ * C_;       // [B,H,N,N]

    float *p_xr, *p_xk, *p_xv, *p_xg2;
    float *p_r, *p_k, *p_v, *p_wout, *p_aout, *p_vout, *p_g, *p_y;
    float *p_hw, *p_ha, *p_hv, *p_hg;
    cudaGetSymbolAddress((void**)&p_xr, g_xr);
    cudaGetSymbolAddress((void**)&p_xk, g_xk);
    cudaGetSymbolAddress((void**)&p_xv, g_xv);
    cudaGetSymbolAddress((void**)&p_xg2, g_xg);
    cudaGetSymbolAddress((void**)&p_r,  g_r);
    cudaGetSymbolAddress((void**)&p_k,  g_k);
    cudaGetSymbolAddress((void**)&p_v,  g_v);
    cudaGetSymbolAddress((void**)&p_wout, g_wout);
    cudaGetSymbolAddress((void**)&p_aout, g_aout);
    cudaGetSymbolAddress((void**)&p_vout, g_vout);
    cudaGetSymbolAddress((void**)&p_g,  g_g);
    cudaGetSymbolAddress((void**)&p_y,  g_y);
    cudaGetSymbolAddress((void**)&p_hw, g_hw);
    cudaGetSymbolAddress((void**)&p_ha, g_ha);
    cudaGetSymbolAddress((void**)&p_hv, g_hv);
    cudaGetSymbolAddress((void**)&p_hg, g_hg);

    // 1) token shift + mixes
    mix_kernel<<<(unsigned)(BTC_ / 4 / 256), 256>>>(
        (const float4*)x, (const float4*)shf,
        (const float4*)mr, (const float4*)mw, (const float4*)mk,
        (const float4*)mv, (const float4*)ma, (const float4*)mg);

    dim3 gBig(C_ / 128, M_ / 128);

    // 2) big projections
    sgemm128<<<gBig, 256>>>(p_xr, Wr, p_r, M_, C_, C_);
    sgemm128<<<gBig, 256>>>(p_xk, Wk, p_k, M_, C_, C_);
    sgemm128<<<gBig, 256>>>(p_xv, Wv, p_v, M_, C_, C_);

    // 3) fused low-rank stage 1 (w1:tanh, a1, v1, g1:sigmoid)
    s1_kernel<<<dim3(4, M_ / 128, 4), 256>>>(w1, a1, v1, g1);

    // 4) low-rank stage 2
    sgemm128<<<gBig, 256>>>(p_hw, w2, p_wout, M_, C_, 64);
    sgemm128<<<gBig, 256>>>(p_ha, a2, p_aout, M_, C_, 64);
    sgemm128<<<gBig, 256>>>(p_hv, v2, p_vout, M_, C_, 32);
    sgemm128<<<gBig, 256>>>(p_hg, g2, p_g,    M_, C_, 128);

    // 5) elementwise post + bf16 staging
    post_kernel<<<(B_ * T_ * H_) / 8, 256>>>(vf, w0, a0, v0, kkm, kam);

    // 6) recurrence (also writes final state to d_out)
    scan_kernel<<<B_ * H_, 128>>>(wkv0, out_S);

    // 7) GroupNorm + bonus + gate
    gn_kernel<<<(B_ * T_ * H_) / 8, 256>>>(rk, lnw, lnb);

    // 8) output projection straight into d_out + x[:, -1]
    sgemm128<<<gBig, 256>>>(p_y, Wo, out, M_, C_, C_);
    tail_kernel<<<(B_ * C_) / 256, 256>>>(x, out_x);
}

// round 7
// speedup vs baseline: 1.4701x; 1.0871x over previous
#include <cuda_runtime.h>
#include <cuda_bf16.h>
#include <cstdint>

// ---------------------------------------------------------------------------
// RWKV7 Tmix forward, B=2 T=2048 C=2048 H=32 N=64
//   1) mix_kernel   : token shift + 6 lerps
//   2) rkv_kernel   : r/k/v projections batched (grid.z=3), swizzled-smem GEMM
//   3) s1_kernel    : all 4 low-rank stage-1 GEMMs fused (tanh/sigmoid epi)
//   4) s2_kernel    : low-rank stage-2 batched (grid.z=4)
//   5) post_kernel  : softplus/sigmoid/kk-norm/k,v update + bf16 staging
//   6) scan_kernel  : sequential delta-rule recurrence (packed f32x2, 4-chains)
//   7) gn_kernel    : per-head GroupNorm + r.k.r_k bonus + gate
//   8) wo_kernel    : (y*g) @ W_o -> d_out ; tail_kernel: x[:,-1]
// ---------------------------------------------------------------------------

constexpr int B_ = 2, T_ = 2048, C_ = 2048, H_ = 32, N_ = 64;
constexpr int M_ = B_ * T_;                       // 4096 token rows
constexpr size_t BTC_ = (size_t)B_ * T_ * C_;     // 8,388,608

typedef unsigned long long ull;

// ---- scratch: __device__ globals ------------------------------------------
__device__ float g_xr[BTC_], g_xw[BTC_], g_xk[BTC_], g_xv[BTC_], g_xa[BTC_], g_xg[BTC_];
__device__ float g_r[BTC_], g_k[BTC_], g_v[BTC_];
__device__ float g_wout[BTC_], g_aout[BTC_], g_vout[BTC_], g_g[BTC_];
__device__ float g_o[BTC_], g_y[BTC_];
__device__ float g_hw[M_ * 64], g_ha[M_ * 64], g_hv[M_ * 32], g_hg[M_ * 128];
__device__ __nv_bfloat16 sb_r[BTC_], sb_k[BTC_], sb_v[BTC_], sb_w[BTC_], sb_a[BTC_], sb_b[BTC_];

// ---------------------------------------------------------------------------
// packed f32x2 + cp.async helpers
// ---------------------------------------------------------------------------
__device__ __forceinline__ ull pk2dup(float v) {
    ull r; unsigned u = __float_as_uint(v);
    asm("mov.b64 %0, {%1, %2};" : "=l"(r) : "r"(u), "r"(u));
    return r;
}
__device__ __forceinline__ ull pk2(float a, float b) {
    ull r;
    asm("mov.b64 %0, {%1, %2};" : "=l"(r) : "r"(__float_as_uint(a)), "r"(__float_as_uint(b)));
    return r;
}
__device__ __forceinline__ ull ffma2(ull a, ull b, ull c) {
    ull d;
    asm("fma.rn.f32x2 %0, %1, %2, %3;" : "=l"(d) : "l"(a), "l"(b), "l"(c));
    return d;
}
__device__ __forceinline__ ull mul2(ull a, ull b) {
    ull d;
    asm("mul.rn.f32x2 %0, %1, %2;" : "=l"(d) : "l"(a), "l"(b));
    return d;
}
__device__ __forceinline__ ull add2(ull a, ull b) {
    ull d;
    asm("add.rn.f32x2 %0, %1, %2;" : "=l"(d) : "l"(a), "l"(b));
    return d;
}
__device__ __forceinline__ float2 upk2(ull v) {
    unsigned lo, hi;
    asm("mov.b64 {%0, %1}, %2;" : "=r"(lo), "=r"(hi) : "l"(v));
    return make_float2(__uint_as_float(lo), __uint_as_float(hi));
}
__device__ __forceinline__ void cp16(uint32_t s, const void* g) {
    asm volatile("cp.async.cg.shared.global [%0], [%1], 16;" :: "r"(s), "l"(g));
}
__device__ __forceinline__ void cp_commit() { asm volatile("cp.async.commit_group;"); }
__device__ __forceinline__ void cp_wait0()  { asm volatile("cp.async.wait_group 0;"); }

__device__ __forceinline__ float sigm(float x) { return 1.f / (1.f + expf(-x)); }
__device__ __forceinline__ float wredsum(float v) {
#pragma unroll
    for (int o = 16; o; o >>= 1) v += __shfl_xor_sync(0xffffffffu, v, o);
    return v;
}

// ---------------------------------------------------------------------------
// 1) token shift + mixes (vectorized float4)
// ---------------------------------------------------------------------------
__global__ void __launch_bounds__(256) mix_kernel(
    const float4* __restrict__ x4, const float4* __restrict__ sh4,
    const float4* __restrict__ mr, const float4* __restrict__ mw,
    const float4* __restrict__ mk, const float4* __restrict__ mv,
    const float4* __restrict__ ma, const float4* __restrict__ mg)
{
    size_t i = (size_t)blockIdx.x * 256 + threadIdx.x;   // over BTC/4
    int c4 = (int)(i & 511);                              // C/4 = 512
    size_t bt = i >> 9;
    int t = (int)(bt & (T_ - 1));
    float4 xv = x4[i];
    float4 pv = (t == 0) ? sh4[(bt >> 11) * 512 + c4] : x4[i - 512];
    float dx = pv.x - xv.x, dy = pv.y - xv.y, dz = pv.z - xv.z, dw = pv.w - xv.w;
#define MIXOUT(dst, mm) { float4 m = (mm)[c4]; float4 o;                         \
        o.x = fmaf(dx, m.x, xv.x); o.y = fmaf(dy, m.y, xv.y);                    \
        o.z = fmaf(dz, m.z, xv.z); o.w = fmaf(dw, m.w, xv.w);                    \
        ((float4*)(dst))[i] = o; }
    MIXOUT(g_xr, mr) MIXOUT(g_xw, mw) MIXOUT(g_xk, mk)
    MIXOUT(g_xv, mv) MIXOUT(g_xa, ma) MIXOUT(g_xg, mg)
#undef MIXOUT
}

// ---------------------------------------------------------------------------
// GEMM core: 128x128 tile, BK=16, cp.async double-buffered.
// As: [m][16] k-major, 64B rows, quadrant-XOR swizzle (q ^ ((m>>3)&3)) so the
//     4 stride-512B rows a warp touches per LDS.64 land in distinct banks.
// Bs: [k][128] natural. Lane map: warp = 4 trow x 8 tcol -> B LDS.128 dedups
//     to 128B (1 crossbar cycle), A LDS.64 broadcast conflict-free.
// Crossbar ~6 cyc/warp/kk vs fma-pipe 16 -> FMA-paced.
// ---------------------------------------------------------------------------
__device__ __forceinline__ void gemm_load_tile(
    uint32_t sAs, uint32_t sBs, const float* Abase, const float* Bbase,
    int K, int N, int kt, int s, int tid)
{
    const int ci1 = tid + 256;
    const int m0 = tid >> 2, q0 = tid & 3;
    const int m1 = ci1 >> 2, q1 = ci1 & 3;
    cp16(sAs + s * 8192 + m0 * 64 + ((q0 ^ ((m0 >> 3) & 3)) << 4),
         Abase + (size_t)m0 * K + kt + q0 * 4);
    cp16(sAs + s * 8192 + m1 * 64 + ((q1 ^ ((m1 >> 3) & 3)) << 4),
         Abase + (size_t)m1 * K + kt + q1 * 4);
    const int r0 = tid >> 5, c0 = tid & 31;
    const int r1 = ci1 >> 5, c1 = ci1 & 31;
    cp16(sBs + s * 8192 + r0 * 512 + c0 * 16, Bbase + (size_t)(kt + r0) * N + c0 * 4);
    cp16(sBs + s * 8192 + r1 * 512 + c1 * 16, Bbase + (size_t)(kt + r1) * N + c1 * 4);
    cp_commit();
}

__device__ __forceinline__ void gemm_tile(
    const float* __restrict__ A, const float* __restrict__ Bm,
    float* __restrict__ Cm, int N, int K)
{
    __shared__ __align__(16) float As[2][128 * 16];
    __shared__ __align__(16) float Bs[2][16 * 128];

    const int tid  = threadIdx.x;
    // warp-internal: 4 distinct trow, 8 distinct tcol (bijective over 256)
    const int trow = ((tid >> 5) & 3) * 4 + ((tid >> 3) & 3);
    const int tcol = ((tid >> 7) << 3) + (tid & 7);
    const int rowBase = blockIdx.y * 128;
    const int colBase = blockIdx.x * 128;

    const uint32_t sAs = (uint32_t)__cvta_generic_to_shared(As);
    const uint32_t sBs = (uint32_t)__cvta_generic_to_shared(Bs);
    const float* Abase = A + (size_t)rowBase * K;
    const float* Bbase = Bm + colBase;

    ull acc[8][4];
#pragma unroll
    for (int i = 0; i < 8; i++)
#pragma unroll
        for (int j = 0; j < 4; j++) acc[i][j] = 0ull;

    const int NT = K / 16;
    gemm_load_tile(sAs, sBs, Abase, Bbase, K, N, 0, 0, tid);
    for (int t = 0; t < NT; t++) {
        cp_wait0();
        __syncthreads();
        if (t + 1 < NT)
            gemm_load_tile(sAs, sBs, Abase, Bbase, K, N, (t + 1) * 16, (t + 1) & 1, tid);
        const char* asb = (const char*)(As[t & 1]) + trow * 8 * 64;
        const int sw = (trow & 3) << 4;
        const float* bs = Bs[t & 1] + tcol * 8;
#pragma unroll
        for (int kk2 = 0; kk2 < 8; kk2++) {
            ull ap[8];
#pragma unroll
            for (int i = 0; i < 8; i++)
                ap[i] = *(const ull*)(asb + i * 64 + ((kk2 * 8) ^ sw));
#pragma unroll
            for (int s = 0; s < 2; s++) {
                const ulonglong2* bp =
                    (const ulonglong2*)(bs + (kk2 * 2 + s) * 128);
                const ulonglong2 bq0 = bp[0], bq1 = bp[1];
#pragma unroll
                for (int i = 0; i < 8; i++) {
                    float2 af = upk2(ap[i]);
                    ull ad = pk2dup(s ? af.y : af.x);
                    acc[i][0] = ffma2(ad, bq0.x, acc[i][0]);
                    acc[i][1] = ffma2(ad, bq0.y, acc[i][1]);
                    acc[i][2] = ffma2(ad, bq1.x, acc[i][2]);
                    acc[i][3] = ffma2(ad, bq1.y, acc[i][3]);
                }
            }
        }
        __syncthreads();
    }

#pragma unroll
    for (int i = 0; i < 8; i++) {
        float* crow = Cm + (size_t)(rowBase + trow * 8 + i) * N + colBase + tcol * 8;
        float2 v0 = upk2(acc[i][0]), v1 = upk2(acc[i][1]);
        float2 v2 = upk2(acc[i][2]), v3 = upk2(acc[i][3]);
        *(float4*)crow       = make_float4(v0.x, v0.y, v1.x, v1.y);
        *(float4*)(crow + 4) = make_float4(v2.x, v2.y, v3.x, v3.y);
    }
}

// 2) r/k/v projections batched over grid.z
__global__ void __launch_bounds__(256, 2) rkv_kernel(
    const float* __restrict__ Wr, const float* __restrict__ Wk,
    const float* __restrict__ Wv)
{
    const int z = blockIdx.z;
    const float* A = (z == 0) ? g_xr : (z == 1) ? g_xk : g_xv;
    const float* B = (z == 0) ? Wr   : (z == 1) ? Wk   : Wv;
    float*       C = (z == 0) ? g_r  : (z == 1) ? g_k  : g_v;
    gemm_tile(A, B, C, C_, C_);
}

// 4) low-rank stage-2 batched over grid.z
__global__ void __launch_bounds__(256, 2) s2_kernel(
    const float* __restrict__ w2, const float* __restrict__ a2,
    const float* __restrict__ v2, const float* __restrict__ g2)
{
    const int z = blockIdx.z;
    const float* A = (z == 0) ? g_hw   : (z == 1) ? g_ha   : (z == 2) ? g_hv   : g_hg;
    const float* B = (z == 0) ? w2     : (z == 1) ? a2     : (z == 2) ? v2     : g2;
    float*       C = (z == 0) ? g_wout : (z == 1) ? g_aout : (z == 2) ? g_vout : g_g;
    const int    K = (z == 2) ? 32 : (z == 3) ? 128 : 64;
    gemm_tile(A, B, C, C_, K);
}

// 8) output projection
__global__ void __launch_bounds__(256, 2) wo_kernel(
    const float* __restrict__ Wo, float* __restrict__ out)
{
    gemm_tile(g_y, Wo, out, C_, C_);
}

// ---------------------------------------------------------------------------
// 3) fused stage-1 low-rank GEMMs: z selects {w1:tanh, a1, v1, g1:sigmoid}.
//    BM=128, BN=32, BK=16, K=2048. grid (4, M/128, 4); excess x-tiles exit.
// ---------------------------------------------------------------------------
__global__ void __launch_bounds__(256, 2) s1_kernel(
    const float* __restrict__ w1, const float* __restrict__ a1,
    const float* __restrict__ v1, const float* __restrict__ g1)
{
    constexpr int BM = 128, BN = 32, BK = 16, BKP = 20, K = C_;
    const int z = blockIdx.z;
    const int Nz = (z == 2) ? 32 : (z == 3 ? 128 : 64);
    if (blockIdx.x * BN >= Nz) return;

    const float* A  = (z == 0) ? g_xw : (z == 1) ? g_xa : (z == 2) ? g_xv : g_xg;
    const float* Bm = (z == 0) ? w1   : (z == 1) ? a1   : (z == 2) ? v1   : g1;
    float* Cm       = (z == 0) ? g_hw : (z == 1) ? g_ha : (z == 2) ? g_hv : g_hg;

    __shared__ __align__(16) float As[2][BM * BKP];
    __shared__ __align__(16) float Bs[2][BK * BN];

    const int tid  = threadIdx.x;
    const int trow = tid >> 3;       // 0..31 -> 4 rows each
    const int tcol = tid & 7;        // 0..7  -> 4 cols each
    const int rowBase = blockIdx.y * BM;
    const int colBase = blockIdx.x * BN;

    const uint32_t sAs = (uint32_t)__cvta_generic_to_shared(As);
    const uint32_t sBs = (uint32_t)__cvta_generic_to_shared(Bs);
    const int am0 = tid >> 2,         ac0 = (tid & 3) * 4;
    const int am1 = (tid + 256) >> 2, ac1 = ((tid + 256) & 3) * 4;
    const int br = tid >> 3, bc = (tid & 7) * 4;      // tid<128 loads B
    const float* Abase = A + (size_t)rowBase * K;
    const float* Bbase = Bm + colBase;

    ull acc[4][2];
#pragma unroll
    for (int i = 0; i < 4; i++) { acc[i][0] = 0ull; acc[i][1] = 0ull; }

#define LOAD_TILE1(kt, s) {                                                       \
        cp16(sAs + ((s) * BM * BKP + am0 * BKP + ac0) * 4,                        \
             Abase + (size_t)am0 * K + (kt) + ac0);                               \
        cp16(sAs + ((s) * BM * BKP + am1 * BKP + ac1) * 4,                        \
             Abase + (size_t)am1 * K + (kt) + ac1);                               \
        if (tid < 128)                                                            \
            cp16(sBs + ((s) * BK * BN + br * BN + bc) * 4,                        \
                 Bbase + (size_t)((kt) + br) * Nz + bc);                          \
        cp_commit(); }

    const int NT = K / BK;
    LOAD_TILE1(0, 0)
    for (int t = 0; t < NT; t++) {
        cp_wait0();
        __syncthreads();
        if (t + 1 < NT) LOAD_TILE1((t + 1) * BK, (t + 1) & 1)
        const float* as = As[t & 1] + trow * 4 * BKP;
        const float* bs = Bs[t & 1] + tcol * 4;
#pragma unroll
        for (int kk = 0; kk < BK; kk++) {
            const ull* bp = (const ull*)(bs + kk * BN);
            ull b0 = bp[0], b1 = bp[1];
#pragma unroll
            for (int i = 0; i < 4; i++) {
                ull ad = pk2dup(as[i * BKP + kk]);
                acc[i][0] = ffma2(ad, b0, acc[i][0]);
                acc[i][1] = ffma2(ad, b1, acc[i][1]);
            }
        }
        __syncthreads();
    }
#undef LOAD_TILE1

#pragma unroll
    for (int i = 0; i < 4; i++) {
        float* crow = Cm + (size_t)(rowBase + trow * 4 + i) * Nz + colBase + tcol * 4;
        float2 v0 = upk2(acc[i][0]), v1 = upk2(acc[i][1]);
        float4 o = make_float4(v0.x, v0.y, v1.x, v1.y);
        if (z == 0) { o.x = tanhf(o.x); o.y = tanhf(o.y); o.z = tanhf(o.z); o.w = tanhf(o.w); }
        if (z == 3) { o.x = sigm(o.x);  o.y = sigm(o.y);  o.z = sigm(o.z);  o.w = sigm(o.w); }
        *(float4*)crow = o;
    }
}

// ---------------------------------------------------------------------------
// 5) post-GEMM elementwise: one warp per (b,t,h), 2 channels per lane.
// ---------------------------------------------------------------------------
__global__ void __launch_bounds__(256) post_kernel(
    const float* __restrict__ v_first, const float* __restrict__ w0,
    const float* __restrict__ a0, const float* __restrict__ v0,
    const float* __restrict__ kkm, const float* __restrict__ kam)
{
    int g = blockIdx.x * 8 + (threadIdx.x >> 5);          // (b*T+t)*H + h
    int lane = threadIdx.x & 31;
    int h = g & (H_ - 1);
    size_t bt = (size_t)(g >> 5);
    size_t i0 = bt * C_ + (size_t)h * N_ + lane, i1 = i0 + 32;
    int c0 = h * N_ + lane, c1 = c0 + 32;

    float kr0 = g_k[i0], kr1 = g_k[i1];
    float kk0 = kr0 * kkm[c0], kk1 = kr1 * kkm[c1];
    float ss = wredsum(kk0 * kk0 + kk1 * kk1);
    float inv = 1.f / fmaxf(sqrtf(ss), 1e-12f);
    kk0 *= inv; kk1 *= inv;

    float aa0 = sigm(a0[c0] + g_aout[i0]);
    float aa1 = sigm(a0[c1] + g_aout[i1]);

    float z0 = w0[c0] + g_wout[i0], z1 = w0[c1] + g_wout[i1];
    float u0 = -z0, u1 = -z1;
    float sp0 = fmaxf(u0, 0.f) + log1pf(expf(-fabsf(u0)));
    float sp1 = fmaxf(u1, 0.f) + log1pf(expf(-fabsf(u1)));
    float ww0 = -sp0 - 0.5f, ww1 = -sp1 - 0.5f;

    float sv0 = sigm(v0[c0] + g_vout[i0]);
    float sv1 = sigm(v0[c1] + g_vout[i1]);
    float vr0 = g_v[i0], vr1 = g_v[i1];
    float vv0 = fmaf(v_first[i0] - vr0, sv0, vr0);
    float vv1 = fmaf(v_first[i1] - vr1, sv1, vr1);
    g_v[i0] = vv0; g_v[i1] = vv1;

    float kn0 = kr0 * fmaf(aa0 - 1.f, kam[c0], 1.f);
    float kn1 = kr1 * fmaf(aa1 - 1.f, kam[c1], 1.f);
    g_k[i0] = kn0; g_k[i1] = kn1;

    sb_r[i0] = __float2bfloat16(g_r[i0]); sb_r[i1] = __float2bfloat16(g_r[i1]);
    sb_k[i0] = __float2bfloat16(kn0);     sb_k[i1] = __float2bfloat16(kn1);
    sb_v[i0] = __float2bfloat16(vv0);     sb_v[i1] = __float2bfloat16(vv1);
    sb_w[i0] = __float2bfloat16(ww0);     sb_w[i1] = __float2bfloat16(ww1);
    sb_a[i0] = __float2bfloat16(-kk0);    sb_a[i1] = __float2bfloat16(-kk1);
    sb_b[i0] = __float2bfloat16(kk0 * aa0); sb_b[i1] = __float2bfloat16(kk1 * aa1);
}

// ---------------------------------------------------------------------------
// 6) sequential scan, packed f32x2 state, 4-way split accumulation chains.
//    One CTA per (b,h); 128 threads; thread (col, half) owns
//    S[half*32 .. +31][col] as 16 f32x2 pairs.
// ---------------------------------------------------------------------------
__global__ void __launch_bounds__(128) scan_kernel(
    const float* __restrict__ wkv0, float* __restrict__ outS)
{
    const int b = blockIdx.x >> 5;       // H=32
    const int h = blockIdx.x & 31;
    const int tid = threadIdx.x;
    const int col = tid >> 1;
    const int half = tid & 1;
    const int ko = half * 32;

    __shared__ __align__(16) float sh[2][6][N_];   // [buf][r,k,v,ew,a,b][n]

    ull S2[16];
    {
        size_t sbase = (((size_t)b * H_ + h) * N_) * N_;
#pragma unroll
        for (int j = 0; j < 16; j++)
            S2[j] = pk2(wkv0[sbase + (size_t)(ko + 2 * j) * N_ + col],
                        wkv0[sbase + (size_t)(ko + 2 * j + 1) * N_ + col]);
    }

    const size_t base = ((size_t)b * T_) * C_ + (size_t)h * N_;
    float pr = 0, pk = 0, pv = 0, pw = 0, pa = 0, pb = 0;
    if (tid < 64) {
        size_t idx = base + tid;
        pr = __bfloat162float(sb_r[idx]); pk = __bfloat162float(sb_k[idx]);
        pv = __bfloat162float(sb_v[idx]); pw = __bfloat162float(sb_w[idx]);
        pa = __bfloat162float(sb_a[idx]); pb = __bfloat162float(sb_b[idx]);
    }
    int buf = 0;
    for (int t = 0; t < T_; t++) {
        if (tid < 64) {
            sh[buf][0][tid] = pr; sh[buf][1][tid] = pk; sh[buf][2][tid] = pv;
            sh[buf][3][tid] = __expf(pw); sh[buf][4][tid] = pa; sh[buf][5][tid] = pb;
            if (t + 1 < T_) {
                size_t idx = base + (size_t)(t + 1) * C_ + tid;
                pr = __bfloat162float(sb_r[idx]); pk = __bfloat162float(sb_k[idx]);
                pv = __bfloat162float(sb_v[idx]); pw = __bfloat162float(sb_w[idx]);
                pa = __bfloat162float(sb_a[idx]); pb = __bfloat162float(sb_b[idx]);
            }
        }
        __syncthreads();
        const ull* r2 = (const ull*)(&sh[buf][0][ko]);
        const ull* k2 = (const ull*)(&sh[buf][1][ko]);
        const ull* e2 = (const ull*)(&sh[buf][3][ko]);
        const ull* a2 = (const ull*)(&sh[buf][4][ko]);
        const ull* b2 = (const ull*)(&sh[buf][5][ko]);

        // sa = a . S(col) : 4 independent chains (depth 4)
        ull sc0 = 0ull, sc1 = 0ull, sc2 = 0ull, sc3 = 0ull;
#pragma unroll
        for (int j = 0; j < 16; j += 4) {
            sc0 = ffma2(a2[j],     S2[j],     sc0);
            sc1 = ffma2(a2[j + 1], S2[j + 1], sc1);
            sc2 = ffma2(a2[j + 2], S2[j + 2], sc2);
            sc3 = ffma2(a2[j + 3], S2[j + 3], sc3);
        }
        float2 sp = upk2(add2(add2(sc0, sc1), add2(sc2, sc3)));
        float sa = sp.x + sp.y;
        sa += __shfl_xor_sync(0xffffffffu, sa, 1);

        const float vt = sh[buf][2][col];
        const ull sad = pk2dup(sa), vtd = pk2dup(vt);
        ull o0 = 0ull, o1 = 0ull, o2 = 0ull, o3 = 0ull;
#pragma unroll
        for (int j = 0; j < 16; j += 4) {
            ull t0 = ffma2(b2[j],     sad, mul2(k2[j],     vtd));
            ull t1 = ffma2(b2[j + 1], sad, mul2(k2[j + 1], vtd));
            ull t2 = ffma2(b2[j + 2], sad, mul2(k2[j + 2], vtd));
            ull t3 = ffma2(b2[j + 3], sad, mul2(k2[j + 3], vtd));
            S2[j]     = ffma2(S2[j],     e2[j],     t0);
            S2[j + 1] = ffma2(S2[j + 1], e2[j + 1], t1);
            S2[j + 2] = ffma2(S2[j + 2], e2[j + 2], t2);
            S2[j + 3] = ffma2(S2[j + 3], e2[j + 3], t3);
            o0 = ffma2(r2[j],     S2[j],     o0);
            o1 = ffma2(r2[j + 1], S2[j + 1], o1);
            o2 = ffma2(r2[j + 2], S2[j + 2], o2);
            o3 = ffma2(r2[j + 3], S2[j + 3], o3);
        }
        float2 op = upk2(add2(add2(o0, o1), add2(o2, o3)));
        float o = op.x + op.y;
        o += __shfl_xor_sync(0xffffffffu, o, 1);
        if (half == 0) g_o[base + (size_t)t * C_ + col] = o;
        buf ^= 1;
    }
    {
        size_t sbase = (((size_t)b * H_ + h) * N_) * N_;
#pragma unroll
        for (int j = 0; j < 16; j++) {
            float2 v = upk2(S2[j]);
            outS[sbase + (size_t)(ko + 2 * j) * N_ + col]     = v.x;
            outS[sbase + (size_t)(ko + 2 * j + 1) * N_ + col] = v.y;
        }
    }
}

// ---------------------------------------------------------------------------
// 7) GroupNorm (per head) + r.k.r_k bonus + gate
// ---------------------------------------------------------------------------
__global__ void __launch_bounds__(256) gn_kernel(
    const float* __restrict__ rk, const float* __restrict__ lnw,
    const float* __restrict__ lnb)
{
    int g = blockIdx.x * 8 + (threadIdx.x >> 5);
    int lane = threadIdx.x & 31;
    int h = g & (H_ - 1);
    size_t bt = (size_t)(g >> 5);
    size_t i0 = bt * C_ + (size_t)h * N_ + lane, i1 = i0 + 32;
    int c0 = h * N_ + lane, c1 = c0 + 32;

    float o0 = g_o[i0], o1 = g_o[i1];
    float mu = wredsum(o0 + o1) * (1.f / 64.f);
    float d0 = o0 - mu, d1 = o1 - mu;
    float var = wredsum(d0 * d0 + d1 * d1) * (1.f / 64.f);
    float inv = 1.f / sqrtf(var + 6.4e-4f);    // EPS_GN = 1e-5 * 8^2
    float y0 = fmaf(d0 * inv, lnw[c0], lnb[c0]);
    float y1 = fmaf(d1 * inv, lnw[c1], lnb[c1]);
    float dot = wredsum(g_r[i0] * g_k[i0] * rk[c0] + g_r[i1] * g_k[i1] * rk[c1]);
    y0 = fmaf(dot, g_v[i0], y0);
    y1 = fmaf(dot, g_v[i1], y1);
    g_y[i0] = y0 * g_g[i0];
    g_y[i1] = y1 * g_g[i1];
}

// 8b) x[:, -1] passthrough
__global__ void tail_kernel(const float* __restrict__ x, float* __restrict__ outx) {
    int i = blockIdx.x * 256 + threadIdx.x;   // B*C = 4096
    int b = i >> 11, c = i & (C_ - 1);
    outx[i] = x[((size_t)b * T_ + (T_ - 1)) * C_ + c];
}

// ---------------------------------------------------------------------------
extern "C" void kernel_launch(void* const* d_in, const int* in_sizes, int n_in,
                              void* d_out, int out_size) {
    const float* x    = (const float*)d_in[0];
    const float* shf  = (const float*)d_in[1];
    const float* wkv0 = (const float*)d_in[2];
    const float* vf   = (const float*)d_in[3];
    const float* mr   = (const float*)d_in[4];
    const float* mw   = (const float*)d_in[5];
    const float* mk   = (const float*)d_in[6];
    const float* mv   = (const float*)d_in[7];
    const float* ma   = (const float*)d_in[8];
    const float* mg   = (const float*)d_in[9];
    const float* w0   = (const float*)d_in[10];
    const float* w1   = (const float*)d_in[11];
    const float* w2   = (const float*)d_in[12];
    const float* a0   = (const float*)d_in[13];
    const float* a1   = (const float*)d_in[14];
    const float* a2   = (const float*)d_in[15];
    const float* v0   = (const float*)d_in[16];
    const float* v1   = (const float*)d_in[17];
    const float* v2   = (const float*)d_in[18];
    const float* g1   = (const float*)d_in[19];
    const float* g2   = (const float*)d_in[20];
    const float* kkm  = (const float*)d_in[21];
    const float* kam  = (const float*)d_in[22];
    const float* rk   = (const float*)d_in[23];
    const float* Wr   = (const float*)d_in[24];
    const float* Wk   = (const float*)d_in[25];
    const float* Wv   = (const float*)d_in[26];
    const float* Wo   = (const float*)d_in[27];
    const float* lnw  = (const float*)d_in[28];
    const float* lnb  = (const float*)d_in[29];

    float* out   = (float*)d_out;                 // [B,T,C]
    float* out_x = out + BTC_;                    // [B,C]
    float* out_S = out_x + (size_t)B_ * C_;       // [B,H,N,N]

    // 1) token shift + mixes
    mix_kernel<<<(unsigned)(BTC_ / 4 / 256), 256>>>(
        (const float4*)x, (const float4*)shf,
        (const float4*)mr, (const float4*)mw, (const float4*)mk,
        (const float4*)mv, (const float4*)ma, (const float4*)mg);

    // 2) big projections r/k/v, batched (1536 CTAs -> better wave packing)
    rkv_kernel<<<dim3(C_ / 128, M_ / 128, 3), 256>>>(Wr, Wk, Wv);

    // 3) fused low-rank stage 1 (w1:tanh, a1, v1, g1:sigmoid)
    s1_kernel<<<dim3(4, M_ / 128, 4), 256>>>(w1, a1, v1, g1);

    // 4) low-rank stage 2, batched
    s2_kernel<<<dim3(C_ / 128, M_ / 128, 4), 256>>>(w2, a2, v2, g2);

    // 5) elementwise post + bf16 staging
    post_kernel<<<(B_ * T_ * H_) / 8, 256>>>(vf, w0, a0, v0, kkm, kam);

    // 6) recurrence (also writes final state to d_out)
    scan_kernel<<<B_ * H_, 128>>>(wkv0, out_S);

    // 7) GroupNorm + bonus + gate
    gn_kernel<<<(B_ * T_ * H_) / 8, 256>>>(rk, lnw, lnb);

    // 8) output projection straight into d_out + x[:, -1]
    wo_kernel<<<dim3(C_ / 128, M_ / 128), 256>>>(Wo, out);
    tail_kernel<<<(B_ * C_) / 256, 256>>>(x, out_x);
}